// round 1
// baseline (speedup 1.0000x reference)
#include <cuda_runtime.h>
#include <cstdint>

// Problem constants (from reference): F=128, H=64, edges = B*At*Nbr = 524288.
#define F_DIM 128
#define H_DIM 64
#define TILE_E 128          // edges per CTA = 2 atoms * 64 neighbors
#define THREADS 256
#define XS_STRIDE 132       // padded row stride for X tile (floats)
#define WS_STRIDE 68        // padded row stride for W1 tile (floats)

// ---------- packed f32x2 helpers (Blackwell) ----------
__device__ __forceinline__ unsigned long long pack2(float x) {
    unsigned long long r;
    asm("mov.b64 %0, {%1, %1};" : "=l"(r) : "f"(x));
    return r;
}
__device__ __forceinline__ unsigned long long ffma2(unsigned long long a,
                                                    unsigned long long b,
                                                    unsigned long long c) {
    unsigned long long d;
    asm("fma.rn.f32x2 %0, %1, %2, %3;" : "=l"(d) : "l"(a), "l"(b), "l"(c));
    return d;
}
__device__ __forceinline__ void unpack2(unsigned long long v, float& lo, float& hi) {
    asm("mov.b64 {%0, %1}, %2;" : "=f"(lo), "=f"(hi) : "l"(v));
}

// shifted softplus: softplus(x) - ln(2), numerically stable form
__device__ __forceinline__ float ssp(float x) {
    float ax = fabsf(x);
    float l = __logf(1.0f + __expf(-ax));
    return fmaxf(x, 0.0f) + l - 0.69314718055994530942f;
}

__global__ __launch_bounds__(THREADS, 2)
void force_mapping_kernel(const float* __restrict__ X,   // (E, 128)
                          const float* __restrict__ U,   // (E, 3)
                          const float* __restrict__ W1,  // (128, 64)
                          const float* __restrict__ B1,  // (64)
                          const float* __restrict__ W2,  // (64, 1)
                          const float* __restrict__ B2,  // (1)
                          float* __restrict__ out)       // (E/64, 3) = (atoms, 3)
{
    extern __shared__ float smem[];
    float* Xs   = smem;                              // TILE_E * XS_STRIDE
    float* Ws   = Xs + TILE_E * XS_STRIDE;           // F_DIM * WS_STRIDE
    float* b1s  = Ws + F_DIM * WS_STRIDE;            // H
    float* W2s  = b1s + H_DIM;                       // H
    float* fms  = W2s + H_DIM;                       // TILE_E
    float* acc6 = fms + TILE_E;                      // 6

    const int tid = threadIdx.x;
    const int g   = blockIdx.x;

    // ---------------- stage X tile [e][k] (row-major, padded) ----------------
    {
        const float4* gx = reinterpret_cast<const float4*>(X + (size_t)g * TILE_E * F_DIM);
        #pragma unroll
        for (int it = 0; it < 16; ++it) {
            int q  = tid + THREADS * it;     // 0..4095
            int e  = q >> 5;                 // 32 float4 per edge row
            int k4 = q & 31;
            float4 v = gx[q];
            *reinterpret_cast<float4*>(&Xs[e * XS_STRIDE + 4 * k4]) = v;
        }
        // stage W1 [f][h] (row-major, padded)
        const float4* gw = reinterpret_cast<const float4*>(W1);
        #pragma unroll
        for (int it = 0; it < 8; ++it) {
            int q  = tid + THREADS * it;     // 0..2047
            int f  = q >> 4;                 // 16 float4 per f row
            int h4 = q & 15;
            float4 v = gw[q];
            *reinterpret_cast<float4*>(&Ws[f * WS_STRIDE + 4 * h4]) = v;
        }
        if (tid < H_DIM) { b1s[tid] = B1[tid]; W2s[tid] = W2[tid]; }
        if (tid < 6) acc6[tid] = 0.0f;
    }
    __syncthreads();

    // ---------------- GEMM1: thread tile = 4 edges x 8 h (4 f32x2 pairs) ----------------
    const int tx = tid & 7;     // h chunk: h = tx*8 .. tx*8+7
    const int ty = tid >> 3;    // edge group: e = ty*4 .. ty*4+3

    unsigned long long acc[4][4];
    #pragma unroll
    for (int j = 0; j < 4; ++j)
        #pragma unroll
        for (int p = 0; p < 4; ++p) acc[j][p] = 0ull;

    const float* xr0 = Xs + (ty * 4 + 0) * XS_STRIDE;
    const float* xr1 = xr0 + XS_STRIDE;
    const float* xr2 = xr1 + XS_STRIDE;
    const float* xr3 = xr2 + XS_STRIDE;
    const float* wr  = Ws + tx * 8;

    #pragma unroll 4
    for (int k = 0; k < F_DIM; ++k) {
        // 8 consecutive W1 values for this h chunk, as 4 packed f32x2
        const ulonglong2 wA = *reinterpret_cast<const ulonglong2*>(wr + k * WS_STRIDE);
        const ulonglong2 wB = *reinterpret_cast<const ulonglong2*>(wr + k * WS_STRIDE + 4);

        unsigned long long x0 = pack2(xr0[k]);
        unsigned long long x1 = pack2(xr1[k]);
        unsigned long long x2 = pack2(xr2[k]);
        unsigned long long x3 = pack2(xr3[k]);

        acc[0][0] = ffma2(x0, wA.x, acc[0][0]);
        acc[0][1] = ffma2(x0, wA.y, acc[0][1]);
        acc[0][2] = ffma2(x0, wB.x, acc[0][2]);
        acc[0][3] = ffma2(x0, wB.y, acc[0][3]);

        acc[1][0] = ffma2(x1, wA.x, acc[1][0]);
        acc[1][1] = ffma2(x1, wA.y, acc[1][1]);
        acc[1][2] = ffma2(x1, wB.x, acc[1][2]);
        acc[1][3] = ffma2(x1, wB.y, acc[1][3]);

        acc[2][0] = ffma2(x2, wA.x, acc[2][0]);
        acc[2][1] = ffma2(x2, wA.y, acc[2][1]);
        acc[2][2] = ffma2(x2, wB.x, acc[2][2]);
        acc[2][3] = ffma2(x2, wB.y, acc[2][3]);

        acc[3][0] = ffma2(x3, wA.x, acc[3][0]);
        acc[3][1] = ffma2(x3, wA.y, acc[3][1]);
        acc[3][2] = ffma2(x3, wB.x, acc[3][2]);
        acc[3][3] = ffma2(x3, wB.y, acc[3][3]);
    }

    // ---------------- epilogue: bias + ssp + dot(W2), reduce over tx (8 lanes) ----------------
    const float b2v = B2[0];
    float fmj[4];
    #pragma unroll
    for (int j = 0; j < 4; ++j) {
        float s = 0.0f;
        #pragma unroll
        for (int p = 0; p < 4; ++p) {
            float lo, hi;
            unpack2(acc[j][p], lo, hi);
            int h0 = tx * 8 + 2 * p;
            s += ssp(lo + b1s[h0])     * W2s[h0];
            s += ssp(hi + b1s[h0 + 1]) * W2s[h0 + 1];
        }
        // reduce over the 8-lane h-group (lanes [8q .. 8q+7])
        s += __shfl_down_sync(0xffffffffu, s, 4);
        s += __shfl_down_sync(0xffffffffu, s, 2);
        s += __shfl_down_sync(0xffffffffu, s, 1);
        fmj[j] = s + b2v;
    }
    if (tx == 0) {
        #pragma unroll
        for (int j = 0; j < 4; ++j) fms[ty * 4 + j] = fmj[j];
    }
    __syncthreads();

    // ---------------- per-edge: fm * unit_vec, reduce over 64 neighbors ----------------
    if (tid < TILE_E) {
        float fm = fms[tid];
        const float* up = U + ((size_t)g * TILE_E + tid) * 3;
        float v0 = fm * up[0];
        float v1 = fm * up[1];
        float v2 = fm * up[2];
        // each warp covers 32 edges of a single atom (atom = tid>>6)
        #pragma unroll
        for (int off = 16; off > 0; off >>= 1) {
            v0 += __shfl_down_sync(0xffffffffu, v0, off);
            v1 += __shfl_down_sync(0xffffffffu, v1, off);
            v2 += __shfl_down_sync(0xffffffffu, v2, off);
        }
        if ((tid & 31) == 0) {
            int atom = tid >> 6;   // 0 or 1 within this CTA
            atomicAdd(&acc6[atom * 3 + 0], v0);
            atomicAdd(&acc6[atom * 3 + 1], v1);
            atomicAdd(&acc6[atom * 3 + 2], v2);
        }
    }
    __syncthreads();

    // CTA exclusively owns atoms 2g and 2g+1 -> direct store, no global atomics
    if (tid < 6) out[(size_t)g * 6 + tid] = acc6[tid];
}

extern "C" void kernel_launch(void* const* d_in, const int* in_sizes, int n_in,
                              void* d_out, int out_size) {
    const float* X  = (const float*)d_in[0];   // last_edge_embedding (B,At,Nbr,F)
    const float* U  = (const float*)d_in[1];   // unit_vecs           (B,At,Nbr,3)
    const float* W1 = (const float*)d_in[2];   // (F,H)
    const float* B1 = (const float*)d_in[3];   // (H,)
    const float* W2 = (const float*)d_in[4];   // (H,1)
    const float* B2 = (const float*)d_in[5];   // (1,)
    float* out = (float*)d_out;                // (B,At,3)

    const int edges  = in_sizes[1] / 3;        // 524288
    const int blocks = edges / TILE_E;         // 4096

    const size_t smem_bytes =
        (size_t)(TILE_E * XS_STRIDE + F_DIM * WS_STRIDE + H_DIM + H_DIM + TILE_E + 8)
        * sizeof(float);

    cudaFuncSetAttribute(force_mapping_kernel,
                         cudaFuncAttributeMaxDynamicSharedMemorySize,
                         (int)smem_bytes);

    force_mapping_kernel<<<blocks, THREADS, smem_bytes>>>(X, U, W1, B1, W2, B2, out);
}

// round 3
// speedup vs baseline: 1.3538x; 1.3538x over previous
#include <cuda_runtime.h>
#include <cstdint>

// F=128, H=64, edges = B*At*Nbr = 524288.
#define F_DIM 128
#define H_DIM 64
#define TILE_E 128          // edges per CTA = 2 atoms * 64 neighbors
#define THREADS 128
#define XS_STRIDE 132       // X tile row stride (floats); 132 mod 32 = 4 -> consecutive rows conflict-free
#define WS_STRIDE 68        // W tile row stride (floats)

// ---------- packed f32x2 helpers (Blackwell) ----------
__device__ __forceinline__ unsigned long long pack2(float x) {
    unsigned long long r;
    asm("mov.b64 %0, {%1, %1};" : "=l"(r) : "f"(x));
    return r;
}
__device__ __forceinline__ unsigned long long ffma2(unsigned long long a,
                                                    unsigned long long b,
                                                    unsigned long long c) {
    unsigned long long d;
    asm("fma.rn.f32x2 %0, %1, %2, %3;" : "=l"(d) : "l"(a), "l"(b), "l"(c));
    return d;
}
__device__ __forceinline__ void unpack2(unsigned long long v, float& lo, float& hi) {
    asm("mov.b64 {%0, %1}, %2;" : "=f"(lo), "=f"(hi) : "l"(v));
}

// shifted softplus: softplus(x) - ln(2)
__device__ __forceinline__ float ssp(float x) {
    float ax = fabsf(x);
    float l = __logf(1.0f + __expf(-ax));
    return fmaxf(x, 0.0f) + l - 0.69314718055994530942f;
}

__global__ __launch_bounds__(THREADS, 2)
void force_mapping_kernel(const float* __restrict__ X,   // (E, 128)
                          const float* __restrict__ U,   // (E, 3)
                          const float* __restrict__ W1,  // (128, 64)
                          const float* __restrict__ B1,  // (64)
                          const float* __restrict__ W2,  // (64, 1)
                          const float* __restrict__ B2,  // (1)
                          float* __restrict__ out)       // (atoms, 3)
{
    extern __shared__ float smem[];
    float* Xs   = smem;                              // TILE_E * XS_STRIDE
    float* Ws   = Xs + TILE_E * XS_STRIDE;           // F_DIM * WS_STRIDE
    float* b1s  = Ws + F_DIM * WS_STRIDE;            // 64
    float* W2s  = b1s + H_DIM;                       // 64
    float* fms  = W2s + H_DIM;                       // 128
    float* Us   = fms + TILE_E;                      // 384 (unit vecs)
    float* acc6 = Us + TILE_E * 3;                   // 8

    const int tid = threadIdx.x;
    const int g   = blockIdx.x;
    const int tx  = tid & 7;    // h chunk: h = tx*8 .. tx*8+7
    const int ty  = tid >> 3;   // 0..15; edges e_j = ty + 16*j

    // ---------------- stage tiles ----------------
    {
        const float4* gx = reinterpret_cast<const float4*>(X + (size_t)g * TILE_E * F_DIM);
        #pragma unroll
        for (int it = 0; it < 32; ++it) {
            int q  = tid + THREADS * it;     // 0..4095
            int e  = q >> 5;                 // 32 float4 per edge row
            int k4 = q & 31;
            float4 v = gx[q];
            *reinterpret_cast<float4*>(&Xs[e * XS_STRIDE + 4 * k4]) = v;
        }
        const float4* gw = reinterpret_cast<const float4*>(W1);
        #pragma unroll
        for (int it = 0; it < 16; ++it) {
            int q  = tid + THREADS * it;     // 0..2047
            int f  = q >> 4;                 // 16 float4 per f row
            int h4 = q & 15;
            float4 v = gw[q];
            *reinterpret_cast<float4*>(&Ws[f * WS_STRIDE + 4 * h4]) = v;
        }
        // unit vecs: 128 edges * 3 = 384 floats = 96 float4 (coalesced)
        const float4* gu = reinterpret_cast<const float4*>(U + (size_t)g * TILE_E * 3);
        if (tid < 96) *reinterpret_cast<float4*>(&Us[tid * 4]) = gu[tid];
        if (tid < H_DIM) { b1s[tid] = B1[tid]; W2s[tid] = W2[tid]; }
        if (tid < 8) acc6[tid] = 0.0f;
    }
    __syncthreads();

    // ---------------- GEMM1: thread tile = 8 edges x 8 h ----------------
    unsigned long long acc[8][4];
    #pragma unroll
    for (int j = 0; j < 8; ++j)
        #pragma unroll
        for (int p = 0; p < 4; ++p) acc[j][p] = 0ull;

    const float* xbase = Xs + ty * XS_STRIDE;
    const float* wbase = Ws + tx * 8;

    #pragma unroll 1
    for (int k0 = 0; k0 < F_DIM; k0 += 4) {
        // X: 8 edges, 4 k's each, one LDS.128 per edge (lanes hit consecutive rows -> no conflict)
        float4 xv[8];
        #pragma unroll
        for (int j = 0; j < 8; ++j)
            xv[j] = *reinterpret_cast<const float4*>(xbase + j * (16 * XS_STRIDE) + k0);

        #pragma unroll
        for (int kk = 0; kk < 4; ++kk) {
            const float* wr = wbase + (k0 + kk) * WS_STRIDE;
            const ulonglong2 wA = *reinterpret_cast<const ulonglong2*>(wr);
            const ulonglong2 wB = *reinterpret_cast<const ulonglong2*>(wr + 4);

            #pragma unroll
            for (int j = 0; j < 8; ++j) {
                float xs = (kk == 0) ? xv[j].x : (kk == 1) ? xv[j].y
                         : (kk == 2) ? xv[j].z : xv[j].w;
                unsigned long long xp = pack2(xs);
                acc[j][0] = ffma2(xp, wA.x, acc[j][0]);
                acc[j][1] = ffma2(xp, wA.y, acc[j][1]);
                acc[j][2] = ffma2(xp, wB.x, acc[j][2]);
                acc[j][3] = ffma2(xp, wB.y, acc[j][3]);
            }
        }
    }

    // ---------------- epilogue: bias + ssp + dot(W2), reduce over 8 tx lanes ----------------
    const float b2v = B2[0];
    float b1l[8], w2l[8];
    #pragma unroll
    for (int p = 0; p < 8; ++p) { b1l[p] = b1s[tx * 8 + p]; w2l[p] = W2s[tx * 8 + p]; }

    #pragma unroll
    for (int j = 0; j < 8; ++j) {
        float s = 0.0f;
        #pragma unroll
        for (int p = 0; p < 4; ++p) {
            float lo, hi;
            unpack2(acc[j][p], lo, hi);
            s += ssp(lo + b1l[2 * p])     * w2l[2 * p];
            s += ssp(hi + b1l[2 * p + 1]) * w2l[2 * p + 1];
        }
        // reduce over 8-lane h-group (width=8 segments align with tx)
        s += __shfl_down_sync(0xffffffffu, s, 4, 8);
        s += __shfl_down_sync(0xffffffffu, s, 2, 8);
        s += __shfl_down_sync(0xffffffffu, s, 1, 8);
        if (tx == 0) fms[ty + 16 * j] = s + b2v;
    }
    __syncthreads();

    // ---------------- per-edge: fm * unit_vec, reduce 64 neighbors per atom ----------------
    {
        float fm = fms[tid];
        float v0 = fm * Us[tid * 3 + 0];
        float v1 = fm * Us[tid * 3 + 1];
        float v2 = fm * Us[tid * 3 + 2];
        #pragma unroll
        for (int off = 16; off > 0; off >>= 1) {
            v0 += __shfl_down_sync(0xffffffffu, v0, off);
            v1 += __shfl_down_sync(0xffffffffu, v1, off);
            v2 += __shfl_down_sync(0xffffffffu, v2, off);
        }
        if ((tid & 31) == 0) {
            int atom = tid >> 6;   // 0 or 1 within this CTA
            atomicAdd(&acc6[atom * 3 + 0], v0);
            atomicAdd(&acc6[atom * 3 + 1], v1);
            atomicAdd(&acc6[atom * 3 + 2], v2);
        }
    }
    __syncthreads();

    if (tid < 6) out[(size_t)g * 6 + tid] = acc6[tid];
}

extern "C" void kernel_launch(void* const* d_in, const int* in_sizes, int n_in,
                              void* d_out, int out_size) {
    const float* X  = (const float*)d_in[0];
    const float* U  = (const float*)d_in[1];
    const float* W1 = (const float*)d_in[2];
    const float* B1 = (const float*)d_in[3];
    const float* W2 = (const float*)d_in[4];
    const float* B2 = (const float*)d_in[5];
    float* out = (float*)d_out;

    const int edges  = in_sizes[1] / 3;        // 524288
    const int blocks = edges / TILE_E;         // 4096

    const size_t smem_bytes =
        (size_t)(TILE_E * XS_STRIDE + F_DIM * WS_STRIDE + H_DIM + H_DIM
                 + TILE_E + TILE_E * 3 + 8) * sizeof(float);

    cudaFuncSetAttribute(force_mapping_kernel,
                         cudaFuncAttributeMaxDynamicSharedMemorySize,
                         (int)smem_bytes);

    force_mapping_kernel<<<blocks, THREADS, smem_bytes>>>(X, U, W1, B1, W2, B2, out);
}

// round 7
// speedup vs baseline: 2.5250x; 1.8651x over previous
#include <cuda_runtime.h>
#include <cuda_bf16.h>
#include <cstdint>

#define F_DIM 128
#define H_DIM 64
#define TILE_E 128
#define THREADS 128

// ---- dynamic smem byte offsets ----
#define SM_A_HI 0            // 128 rows x 256 B (bf16 X hi), XOR-swizzled
#define SM_A_LO 32768
#define SM_B_HI 65536        // 128 k-rows x 128 B (bf16 W hi), XOR-swizzled
#define SM_B_LO 81920
#define SM_B1   98304        // 64 f
#define SM_W2   98560        // 64 f
#define SM_FMS  98816        // 128 f
#define SM_ACC  99328        // 8 f
#define SM_TOTAL 99360

__device__ __forceinline__ uint32_t smem_u32(const void* p) {
    uint32_t a;
    asm("{ .reg .u64 t; cvta.to.shared.u64 t, %1; cvt.u32.u64 %0, t; }" : "=r"(a) : "l"(p));
    return a;
}
__device__ __forceinline__ uint32_t pack_bf16x2(float lo, float hi) {
    uint32_t r;
    asm("cvt.rn.bf16x2.f32 %0, %1, %2;" : "=r"(r) : "f"(hi), "f"(lo));
    return r;
}
__device__ __forceinline__ void ldmx4(uint32_t addr, uint32_t* r) {
    asm volatile("ldmatrix.sync.aligned.m8n8.x4.shared.b16 {%0,%1,%2,%3}, [%4];"
                 : "=r"(r[0]), "=r"(r[1]), "=r"(r[2]), "=r"(r[3]) : "r"(addr));
}
__device__ __forceinline__ void ldmx2t(uint32_t addr, uint32_t* r) {
    asm volatile("ldmatrix.sync.aligned.m8n8.x2.trans.shared.b16 {%0,%1}, [%2];"
                 : "=r"(r[0]), "=r"(r[1]) : "r"(addr));
}
__device__ __forceinline__ void mma16816(float* c, const uint32_t* a, const uint32_t* b) {
    asm volatile(
        "mma.sync.aligned.m16n8k16.row.col.f32.bf16.bf16.f32 "
        "{%0,%1,%2,%3}, {%4,%5,%6,%7}, {%8,%9}, {%0,%1,%2,%3};"
        : "+f"(c[0]), "+f"(c[1]), "+f"(c[2]), "+f"(c[3])
        : "r"(a[0]), "r"(a[1]), "r"(a[2]), "r"(a[3]), "r"(b[0]), "r"(b[1]));
}
// shifted softplus: softplus(x) - ln(2)
__device__ __forceinline__ float ssp(float x) {
    float ax = fabsf(x);
    float l = __logf(1.0f + __expf(-ax));
    return fmaxf(x, 0.0f) + l - 0.69314718055994530942f;
}

__global__ __launch_bounds__(THREADS, 2)
void force_mapping_kernel(const float* __restrict__ X,
                          const float* __restrict__ U,
                          const float* __restrict__ W1,
                          const float* __restrict__ B1,
                          const float* __restrict__ W2,
                          const float* __restrict__ B2,
                          float* __restrict__ out)
{
    extern __shared__ char smem[];
    const uint32_t sbase = smem_u32(smem);
    const int tid = threadIdx.x;
    const int wid = tid >> 5;
    const int L   = tid & 31;
    const int g   = blockIdx.x;

    float* b1s  = reinterpret_cast<float*>(smem + SM_B1);
    float* W2s  = reinterpret_cast<float*>(smem + SM_W2);
    float* fms  = reinterpret_cast<float*>(smem + SM_FMS);
    float* acc6 = reinterpret_cast<float*>(smem + SM_ACC);

    if (tid < 8) acc6[tid] = 0.0f;

    // ---- convert X tile -> bf16 hi/lo, XOR-swizzled (chunk ^ (row&7)) ----
    {
        const float4* gx = reinterpret_cast<const float4*>(X + (size_t)g * TILE_E * F_DIM);
        #pragma unroll
        for (int it = 0; it < 16; ++it) {
            int q = tid + THREADS * it;          // 8-float group, 0..2047
            int r = q >> 4;                      // edge row 0..127
            int k = (q & 15) * 8;                // k col
            float4 a = gx[q * 2];
            float4 b = gx[q * 2 + 1];
            float xs[8] = {a.x, a.y, a.z, a.w, b.x, b.y, b.z, b.w};
            float hv[8], lv[8];
            #pragma unroll
            for (int j = 0; j < 8; ++j) {
                __nv_bfloat16 h = __float2bfloat16_rn(xs[j]);
                hv[j] = __bfloat162float(h);
                lv[j] = xs[j] - hv[j];
            }
            uint4 H, Lo;
            H.x  = pack_bf16x2(hv[0], hv[1]); H.y  = pack_bf16x2(hv[2], hv[3]);
            H.z  = pack_bf16x2(hv[4], hv[5]); H.w  = pack_bf16x2(hv[6], hv[7]);
            Lo.x = pack_bf16x2(lv[0], lv[1]); Lo.y = pack_bf16x2(lv[2], lv[3]);
            Lo.z = pack_bf16x2(lv[4], lv[5]); Lo.w = pack_bf16x2(lv[6], lv[7]);
            int off = r * 256 + (((k >> 3) ^ (r & 7)) << 4);
            *reinterpret_cast<uint4*>(smem + SM_A_HI + off) = H;
            *reinterpret_cast<uint4*>(smem + SM_A_LO + off) = Lo;
        }
    }
    // ---- convert W1 (K=128 rows x N=64, row-major) -> bf16 hi/lo, swizzled ----
    {
        #pragma unroll
        for (int it = 0; it < 8; ++it) {
            int q  = tid + THREADS * it;         // 0..1023
            int k  = q >> 3;                     // 0..127
            int c  = q & 7;                      // n chunk
            const float4* gw = reinterpret_cast<const float4*>(W1 + k * H_DIM + c * 8);
            float4 a = gw[0];
            float4 b = gw[1];
            float ws[8] = {a.x, a.y, a.z, a.w, b.x, b.y, b.z, b.w};
            float hv[8], lv[8];
            #pragma unroll
            for (int j = 0; j < 8; ++j) {
                __nv_bfloat16 h = __float2bfloat16_rn(ws[j]);
                hv[j] = __bfloat162float(h);
                lv[j] = ws[j] - hv[j];
            }
            uint4 H, Lo;
            H.x  = pack_bf16x2(hv[0], hv[1]); H.y  = pack_bf16x2(hv[2], hv[3]);
            H.z  = pack_bf16x2(hv[4], hv[5]); H.w  = pack_bf16x2(hv[6], hv[7]);
            Lo.x = pack_bf16x2(lv[0], lv[1]); Lo.y = pack_bf16x2(lv[2], lv[3]);
            Lo.z = pack_bf16x2(lv[4], lv[5]); Lo.w = pack_bf16x2(lv[6], lv[7]);
            int off = k * 128 + ((c ^ (k & 7)) << 4);
            *reinterpret_cast<uint4*>(smem + SM_B_HI + off) = H;
            *reinterpret_cast<uint4*>(smem + SM_B_LO + off) = Lo;
        }
        if (tid < H_DIM) { b1s[tid] = B1[tid]; W2s[tid] = W2[tid]; }
    }
    __syncthreads();

    // ---- GEMM1 on tensor pipe: per warp 32 edges x 64 h, K=128, 3 bf16 terms ----
    const int m0  = wid * 32;
    const uint32_t lrow = L & 15;
    const uint32_t lhi  = L >> 4;
    const uint32_t l7   = L & 7;

    const uint32_t aRow0 = sbase + SM_A_HI + (m0 + lrow) * 256;
    const uint32_t aRow1 = aRow0 + 16 * 256;
    const uint32_t bRow  = sbase + SM_B_HI + lrow * 128;

    float acc[2][8][4];
    #pragma unroll
    for (int mt = 0; mt < 2; ++mt)
        #pragma unroll
        for (int nt = 0; nt < 8; ++nt)
            #pragma unroll
            for (int i = 0; i < 4; ++i) acc[mt][nt][i] = 0.0f;

    #pragma unroll
    for (int kt = 0; kt < 8; ++kt) {
        const uint32_t csel = (((kt * 2 + lhi) ^ l7) << 4);
        uint32_t ah0[4], ah1[4], al0[4], al1[4];
        ldmx4(aRow0 + csel, ah0);
        ldmx4(aRow1 + csel, ah1);
        ldmx4(aRow0 + 32768 + csel, al0);
        ldmx4(aRow1 + 32768 + csel, al1);

        const uint32_t bbase = bRow + kt * 2048;
        #pragma unroll
        for (int nt = 0; nt < 8; ++nt) {
            const uint32_t baddr = bbase + ((nt ^ l7) << 4);
            uint32_t bh[2], bl[2];
            ldmx2t(baddr, bh);
            ldmx2t(baddr + 16384, bl);
            mma16816(acc[0][nt], ah0, bh);
            mma16816(acc[1][nt], ah1, bh);
            mma16816(acc[0][nt], ah0, bl);
            mma16816(acc[1][nt], ah1, bl);
            mma16816(acc[0][nt], al0, bh);
            mma16816(acc[1][nt], al1, bh);
        }
    }

    // ---- epilogue: bias + ssp + dot(W2); quad reduce over n ----
    {
        const float b2v = B2[0];
        #pragma unroll
        for (int mt = 0; mt < 2; ++mt) {
            #pragma unroll
            for (int half = 0; half < 2; ++half) {
                float s = 0.0f;
                #pragma unroll
                for (int nt = 0; nt < 8; ++nt) {
                    int h0 = nt * 8 + (L & 3) * 2;
                    float v0 = acc[mt][nt][half * 2 + 0];
                    float v1 = acc[mt][nt][half * 2 + 1];
                    s += ssp(v0 + b1s[h0])     * W2s[h0];
                    s += ssp(v1 + b1s[h0 + 1]) * W2s[h0 + 1];
                }
                s += __shfl_xor_sync(0xffffffffu, s, 1);
                s += __shfl_xor_sync(0xffffffffu, s, 2);
                if ((L & 3) == 0)
                    fms[m0 + mt * 16 + half * 8 + (L >> 2)] = s + b2v;
            }
        }
    }
    __syncthreads();

    // ---- per-edge force vector + 64-neighbor reduction ----
    {
        float fm = fms[tid];
        const float* up = U + ((size_t)g * TILE_E + tid) * 3;
        float v0 = fm * up[0];
        float v1 = fm * up[1];
        float v2 = fm * up[2];
        #pragma unroll
        for (int off = 16; off > 0; off >>= 1) {
            v0 += __shfl_down_sync(0xffffffffu, v0, off);
            v1 += __shfl_down_sync(0xffffffffu, v1, off);
            v2 += __shfl_down_sync(0xffffffffu, v2, off);
        }
        if (L == 0) {
            int atom = tid >> 6;
            atomicAdd(&acc6[atom * 3 + 0], v0);
            atomicAdd(&acc6[atom * 3 + 1], v1);
            atomicAdd(&acc6[atom * 3 + 2], v2);
        }
    }
    __syncthreads();

    if (tid < 6) out[(size_t)g * 6 + tid] = acc6[tid];
}

extern "C" void kernel_launch(void* const* d_in, const int* in_sizes, int n_in,
                              void* d_out, int out_size) {
    const float* X  = (const float*)d_in[0];
    const float* U  = (const float*)d_in[1];
    const float* W1 = (const float*)d_in[2];
    const float* B1 = (const float*)d_in[3];
    const float* W2 = (const float*)d_in[4];
    const float* B2 = (const float*)d_in[5];
    float* out = (float*)d_out;

    const int edges  = in_sizes[1] / 3;     // 524288
    const int blocks = edges / TILE_E;      // 4096

    cudaFuncSetAttribute(force_mapping_kernel,
                         cudaFuncAttributeMaxDynamicSharedMemorySize, SM_TOTAL);

    force_mapping_kernel<<<blocks, THREADS, SM_TOTAL>>>(X, U, W1, B1, W2, B2, out);
}

// round 10
// speedup vs baseline: 3.3010x; 1.3073x over previous
#include <cuda_runtime.h>
#include <cuda_bf16.h>
#include <cstdint>

#define F_DIM 128
#define H_DIM 64
#define TILE_E 128
#define THREADS 128

// ---- dynamic smem byte offsets ----
#define SM_B_HI 0            // 128 k-rows x 128 B (bf16 W hi), XOR-swizzled
#define SM_B_LO 16384
#define SM_B1   32768        // 64 f
#define SM_W2   33024        // 64 f
#define SM_FMS  33280        // 128 f
#define SM_ACC  33792        // 8 f
#define SM_TOTAL 33856

__device__ __forceinline__ uint32_t smem_u32(const void* p) {
    uint32_t a;
    asm("{ .reg .u64 t; cvta.to.shared.u64 t, %1; cvt.u32.u64 %0, t; }" : "=r"(a) : "l"(p));
    return a;
}
__device__ __forceinline__ uint32_t pack_bf16x2(float lo, float hi) {
    uint32_t r;
    asm("cvt.rn.bf16x2.f32 %0, %1, %2;" : "=r"(r) : "f"(hi), "f"(lo));
    return r;
}
// split one float2 into packed bf16x2 hi and lo parts
__device__ __forceinline__ void cvt_split(float2 v, uint32_t& h, uint32_t& l) {
    __nv_bfloat16 hx = __float2bfloat16_rn(v.x);
    __nv_bfloat16 hy = __float2bfloat16_rn(v.y);
    float fhx = __bfloat162float(hx);
    float fhy = __bfloat162float(hy);
    h = pack_bf16x2(fhx, fhy);
    l = pack_bf16x2(v.x - fhx, v.y - fhy);
}
__device__ __forceinline__ void ldmx4t(uint32_t addr, uint32_t* r) {
    asm volatile("ldmatrix.sync.aligned.m8n8.x4.trans.shared.b16 {%0,%1,%2,%3}, [%4];"
                 : "=r"(r[0]), "=r"(r[1]), "=r"(r[2]), "=r"(r[3]) : "r"(addr));
}
__device__ __forceinline__ void mma16816(float* c, const uint32_t* a, const uint32_t* b) {
    asm volatile(
        "mma.sync.aligned.m16n8k16.row.col.f32.bf16.bf16.f32 "
        "{%0,%1,%2,%3}, {%4,%5,%6,%7}, {%8,%9}, {%0,%1,%2,%3};"
        : "+f"(c[0]), "+f"(c[1]), "+f"(c[2]), "+f"(c[3])
        : "r"(a[0]), "r"(a[1]), "r"(a[2]), "r"(a[3]), "r"(b[0]), "r"(b[1]));
}
// shifted softplus: softplus(x) - ln(2)
__device__ __forceinline__ float ssp(float x) {
    float ax = fabsf(x);
    float l = __logf(1.0f + __expf(-ax));
    return fmaxf(x, 0.0f) + l - 0.69314718055994530942f;
}

__global__ __launch_bounds__(THREADS, 3)
void force_mapping_kernel(const float* __restrict__ X,
                          const float* __restrict__ U,
                          const float* __restrict__ W1,
                          const float* __restrict__ B1,
                          const float* __restrict__ W2,
                          const float* __restrict__ B2,
                          float* __restrict__ out)
{
    extern __shared__ char smem[];
    const uint32_t sbase = smem_u32(smem);
    const int tid = threadIdx.x;
    const int wid = tid >> 5;
    const int L   = tid & 31;
    const int g   = blockIdx.x;
    const int m0  = wid * 32;

    float* b1s  = reinterpret_cast<float*>(smem + SM_B1);
    float* W2s  = reinterpret_cast<float*>(smem + SM_W2);
    float* fms  = reinterpret_cast<float*>(smem + SM_FMS);
    float* acc6 = reinterpret_cast<float*>(smem + SM_ACC);

    if (tid < 8) acc6[tid] = 0.0f;

    // ---- A fragment base pointer: row = m0 + L/4, col = (L%4)*2 ----
    const float* xp = X + ((size_t)g * TILE_E + m0 + (L >> 2)) * F_DIM + (L & 3) * 2;

    // pf[buf][j]: j = row{0,8,16,24} x col{+0,+8}, interleaved (r0c0,r0c8,r1c0,...)
    float2 pf[2][8];
    #pragma unroll
    for (int rr = 0; rr < 4; ++rr) {
        const float* rp = xp + rr * 8 * F_DIM;
        pf[0][rr * 2 + 0] = *reinterpret_cast<const float2*>(rp);
        pf[0][rr * 2 + 1] = *reinterpret_cast<const float2*>(rp + 8);
        pf[1][rr * 2 + 0] = *reinterpret_cast<const float2*>(rp + 16);
        pf[1][rr * 2 + 1] = *reinterpret_cast<const float2*>(rp + 24);
    }

    // ---- convert W1 (K=128 rows x N=64, row-major) -> bf16 hi/lo smem, swizzled ----
    {
        #pragma unroll
        for (int it = 0; it < 8; ++it) {
            int q  = tid + THREADS * it;         // 0..1023
            int k  = q >> 3;                     // 0..127
            int c  = q & 7;                      // n chunk (8 floats)
            const float4* gw = reinterpret_cast<const float4*>(W1 + k * H_DIM + c * 8);
            float4 a = gw[0];
            float4 b = gw[1];
            float ws[8] = {a.x, a.y, a.z, a.w, b.x, b.y, b.z, b.w};
            float hv[8], lv[8];
            #pragma unroll
            for (int j = 0; j < 8; ++j) {
                __nv_bfloat16 h = __float2bfloat16_rn(ws[j]);
                hv[j] = __bfloat162float(h);
                lv[j] = ws[j] - hv[j];
            }
            uint4 H, Lo;
            H.x  = pack_bf16x2(hv[0], hv[1]); H.y  = pack_bf16x2(hv[2], hv[3]);
            H.z  = pack_bf16x2(hv[4], hv[5]); H.w  = pack_bf16x2(hv[6], hv[7]);
            Lo.x = pack_bf16x2(lv[0], lv[1]); Lo.y = pack_bf16x2(lv[2], lv[3]);
            Lo.z = pack_bf16x2(lv[4], lv[5]); Lo.w = pack_bf16x2(lv[6], lv[7]);
            int off = k * 128 + ((c ^ (k & 7)) << 4);
            *reinterpret_cast<uint4*>(smem + SM_B_HI + off) = H;
            *reinterpret_cast<uint4*>(smem + SM_B_LO + off) = Lo;
        }
        if (tid < H_DIM) { b1s[tid] = B1[tid]; W2s[tid] = W2[tid]; }
    }
    __syncthreads();

    // ---- GEMM1: per warp 32 edges x 64 h, K=128, 3 bf16 terms ----
    float acc[2][8][4];
    #pragma unroll
    for (int mt = 0; mt < 2; ++mt)
        #pragma unroll
        for (int nt = 0; nt < 8; ++nt)
            #pragma unroll
            for (int i = 0; i < 4; ++i) acc[mt][nt][i] = 0.0f;

    const uint32_t bRow = sbase + SM_B_HI + (L & 15) * 128;
    const uint32_t lsel = L >> 4;
    const uint32_t l7   = L & 7;

    #pragma unroll
    for (int kt = 0; kt < 8; ++kt) {
        // convert current prefetch buffer into A fragments (hi/lo)
        uint32_t ah0[4], ah1[4], al0[4], al1[4];
        {
            float2* cur = pf[kt & 1];
            // mt=0: rows g, g+8  -> cur[0..3]; mt=1: rows g+16, g+24 -> cur[4..7]
            cvt_split(cur[0], ah0[0], al0[0]);   // row g,    cols c0
            cvt_split(cur[2], ah0[1], al0[1]);   // row g+8,  cols c0
            cvt_split(cur[1], ah0[2], al0[2]);   // row g,    cols c0+8
            cvt_split(cur[3], ah0[3], al0[3]);   // row g+8,  cols c0+8
            cvt_split(cur[4], ah1[0], al1[0]);
            cvt_split(cur[6], ah1[1], al1[1]);
            cvt_split(cur[5], ah1[2], al1[2]);
            cvt_split(cur[7], ah1[3], al1[3]);
        }
        // prefetch kt+2
        if (kt < 6) {
            const float* kp = xp + (kt + 2) * 16;
            #pragma unroll
            for (int rr = 0; rr < 4; ++rr) {
                const float* rp = kp + rr * 8 * F_DIM;
                pf[kt & 1][rr * 2 + 0] = *reinterpret_cast<const float2*>(rp);
                pf[kt & 1][rr * 2 + 1] = *reinterpret_cast<const float2*>(rp + 8);
            }
        }

        const uint32_t bbase = bRow + kt * 2048;
        #pragma unroll
        for (int p = 0; p < 4; ++p) {
            // x4.trans: lanes 0-15 -> n-chunk 2p (k rows 0-7, 8-15),
            //           lanes 16-31 -> n-chunk 2p+1
            const uint32_t baddr = bbase + (((2 * p + lsel) ^ l7) << 4);
            uint32_t bh[4], bl[4];
            ldmx4t(baddr, bh);
            ldmx4t(baddr + 16384, bl);

            mma16816(acc[0][2 * p],     ah0, bh);
            mma16816(acc[1][2 * p],     ah1, bh);
            mma16816(acc[0][2 * p + 1], ah0, bh + 2);
            mma16816(acc[1][2 * p + 1], ah1, bh + 2);

            mma16816(acc[0][2 * p],     ah0, bl);
            mma16816(acc[1][2 * p],     ah1, bl);
            mma16816(acc[0][2 * p + 1], ah0, bl + 2);
            mma16816(acc[1][2 * p + 1], ah1, bl + 2);

            mma16816(acc[0][2 * p],     al0, bh);
            mma16816(acc[1][2 * p],     al1, bh);
            mma16816(acc[0][2 * p + 1], al0, bh + 2);
            mma16816(acc[1][2 * p + 1], al1, bh + 2);
        }
    }

    // ---- epilogue: bias + ssp + dot(W2); quad reduce over n ----
    {
        const float b2v = B2[0];
        #pragma unroll
        for (int mt = 0; mt < 2; ++mt) {
            #pragma unroll
            for (int half = 0; half < 2; ++half) {
                float s = 0.0f;
                #pragma unroll
                for (int nt = 0; nt < 8; ++nt) {
                    int h0 = nt * 8 + (L & 3) * 2;
                    float v0 = acc[mt][nt][half * 2 + 0];
                    float v1 = acc[mt][nt][half * 2 + 1];
                    s += ssp(v0 + b1s[h0])     * W2s[h0];
                    s += ssp(v1 + b1s[h0 + 1]) * W2s[h0 + 1];
                }
                s += __shfl_xor_sync(0xffffffffu, s, 1);
                s += __shfl_xor_sync(0xffffffffu, s, 2);
                if ((L & 3) == 0)
                    fms[m0 + mt * 16 + half * 8 + (L >> 2)] = s + b2v;
            }
        }
    }
    __syncthreads();

    // ---- per-edge force vector + 64-neighbor reduction ----
    {
        float fm = fms[tid];
        const float* up = U + ((size_t)g * TILE_E + tid) * 3;
        float v0 = fm * up[0];
        float v1 = fm * up[1];
        float v2 = fm * up[2];
        #pragma unroll
        for (int off = 16; off > 0; off >>= 1) {
            v0 += __shfl_down_sync(0xffffffffu, v0, off);
            v1 += __shfl_down_sync(0xffffffffu, v1, off);
            v2 += __shfl_down_sync(0xffffffffu, v2, off);
        }
        if (L == 0) {
            int atom = tid >> 6;
            atomicAdd(&acc6[atom * 3 + 0], v0);
            atomicAdd(&acc6[atom * 3 + 1], v1);
            atomicAdd(&acc6[atom * 3 + 2], v2);
        }
    }
    __syncthreads();

    if (tid < 6) out[(size_t)g * 6 + tid] = acc6[tid];
}

extern "C" void kernel_launch(void* const* d_in, const int* in_sizes, int n_in,
                              void* d_out, int out_size) {
    const float* X  = (const float*)d_in[0];
    const float* U  = (const float*)d_in[1];
    const float* W1 = (const float*)d_in[2];
    const float* B1 = (const float*)d_in[3];
    const float* W2 = (const float*)d_in[4];
    const float* B2 = (const float*)d_in[5];
    float* out = (float*)d_out;

    const int edges  = in_sizes[1] / 3;     // 524288
    const int blocks = edges / TILE_E;      // 4096

    cudaFuncSetAttribute(force_mapping_kernel,
                         cudaFuncAttributeMaxDynamicSharedMemorySize, SM_TOTAL);

    force_mapping_kernel<<<blocks, THREADS, SM_TOTAL>>>(X, U, W1, B1, W2, B2, out);
}

// round 12
// speedup vs baseline: 3.3114x; 1.0032x over previous
#include <cuda_runtime.h>
#include <cuda_bf16.h>
#include <cstdint>

#define F_DIM 128
#define H_DIM 64
#define TILE_E 128
#define THREADS 128

// ---- dynamic smem byte offsets ----
#define SM_B_HI 0            // 128 k-rows x 128 B (bf16 W hi), XOR-swizzled
#define SM_B_LO 16384
#define SM_B1   32768        // 64 f
#define SM_W2   33024        // 64 f
#define SM_FMS  33280        // 128 f
#define SM_ACC  33792        // 8 f
#define SM_TOTAL 33856

__device__ __forceinline__ uint32_t smem_u32(const void* p) {
    uint32_t a;
    asm("{ .reg .u64 t; cvta.to.shared.u64 t, %1; cvt.u32.u64 %0, t; }" : "=r"(a) : "l"(p));
    return a;
}
__device__ __forceinline__ uint32_t pack_bf16x2(float lo, float hi) {
    uint32_t r;
    asm("cvt.rn.bf16x2.f32 %0, %1, %2;" : "=r"(r) : "f"(hi), "f"(lo));
    return r;
}
// split one float2 into packed bf16x2 hi and lo parts
__device__ __forceinline__ void cvt_split(float2 v, uint32_t& h, uint32_t& l) {
    __nv_bfloat16 hx = __float2bfloat16_rn(v.x);
    __nv_bfloat16 hy = __float2bfloat16_rn(v.y);
    float fhx = __bfloat162float(hx);
    float fhy = __bfloat162float(hy);
    h = pack_bf16x2(fhx, fhy);
    l = pack_bf16x2(v.x - fhx, v.y - fhy);
}
__device__ __forceinline__ void ldmx4t(uint32_t addr, uint32_t* r) {
    asm volatile("ldmatrix.sync.aligned.m8n8.x4.trans.shared.b16 {%0,%1,%2,%3}, [%4];"
                 : "=r"(r[0]), "=r"(r[1]), "=r"(r[2]), "=r"(r[3]) : "r"(addr));
}
__device__ __forceinline__ void mma16816(float* c, const uint32_t* a, const uint32_t* b) {
    asm volatile(
        "mma.sync.aligned.m16n8k16.row.col.f32.bf16.bf16.f32 "
        "{%0,%1,%2,%3}, {%4,%5,%6,%7}, {%8,%9}, {%0,%1,%2,%3};"
        : "+f"(c[0]), "+f"(c[1]), "+f"(c[2]), "+f"(c[3])
        : "r"(a[0]), "r"(a[1]), "r"(a[2]), "r"(a[3]), "r"(b[0]), "r"(b[1]));
}
// shifted softplus: softplus(x) - ln(2)
__device__ __forceinline__ float ssp(float x) {
    float ax = fabsf(x);
    float l = __logf(1.0f + __expf(-ax));
    return fmaxf(x, 0.0f) + l - 0.69314718055994530942f;
}

__global__ __launch_bounds__(THREADS, 3)
void force_mapping_kernel(const float* __restrict__ X,
                          const float* __restrict__ U,
                          const float* __restrict__ W1,
                          const float* __restrict__ B1,
                          const float* __restrict__ W2,
                          const float* __restrict__ B2,
                          float* __restrict__ out)
{
    extern __shared__ char smem[];
    const uint32_t sbase = smem_u32(smem);
    const int tid = threadIdx.x;
    const int wid = tid >> 5;
    const int L   = tid & 31;
    const int g   = blockIdx.x;
    const int m0  = wid * 32;

    float* b1s  = reinterpret_cast<float*>(smem + SM_B1);
    float* W2s  = reinterpret_cast<float*>(smem + SM_W2);
    float* fms  = reinterpret_cast<float*>(smem + SM_FMS);
    float* acc6 = reinterpret_cast<float*>(smem + SM_ACC);

    if (tid < 8) acc6[tid] = 0.0f;

    // ---- A fragment base pointer: row = m0 + L/4, col = (L%4)*2 ----
    const float* xp = X + ((size_t)g * TILE_E + m0 + (L >> 2)) * F_DIM + (L & 3) * 2;

    // pf[buf][j]: j = row{0,8,16,24} x col{+0,+8}, interleaved (r0c0,r0c8,r1c0,...)
    float2 pf[2][8];
    #pragma unroll
    for (int rr = 0; rr < 4; ++rr) {
        const float* rp = xp + rr * 8 * F_DIM;
        pf[0][rr * 2 + 0] = *reinterpret_cast<const float2*>(rp);
        pf[0][rr * 2 + 1] = *reinterpret_cast<const float2*>(rp + 8);
        pf[1][rr * 2 + 0] = *reinterpret_cast<const float2*>(rp + 16);
        pf[1][rr * 2 + 1] = *reinterpret_cast<const float2*>(rp + 24);
    }

    // ---- convert W1 (K=128 rows x N=64, row-major) -> bf16 hi/lo smem, swizzled ----
    {
        #pragma unroll
        for (int it = 0; it < 8; ++it) {
            int q  = tid + THREADS * it;         // 0..1023
            int k  = q >> 3;                     // 0..127
            int c  = q & 7;                      // n chunk (8 floats)
            const float4* gw = reinterpret_cast<const float4*>(W1 + k * H_DIM + c * 8);
            float4 a = gw[0];
            float4 b = gw[1];
            float ws[8] = {a.x, a.y, a.z, a.w, b.x, b.y, b.z, b.w};
            float hv[8], lv[8];
            #pragma unroll
            for (int j = 0; j < 8; ++j) {
                __nv_bfloat16 h = __float2bfloat16_rn(ws[j]);
                hv[j] = __bfloat162float(h);
                lv[j] = ws[j] - hv[j];
            }
            uint4 H, Lo;
            H.x  = pack_bf16x2(hv[0], hv[1]); H.y  = pack_bf16x2(hv[2], hv[3]);
            H.z  = pack_bf16x2(hv[4], hv[5]); H.w  = pack_bf16x2(hv[6], hv[7]);
            Lo.x = pack_bf16x2(lv[0], lv[1]); Lo.y = pack_bf16x2(lv[2], lv[3]);
            Lo.z = pack_bf16x2(lv[4], lv[5]); Lo.w = pack_bf16x2(lv[6], lv[7]);
            int off = k * 128 + ((c ^ (k & 7)) << 4);
            *reinterpret_cast<uint4*>(smem + SM_B_HI + off) = H;
            *reinterpret_cast<uint4*>(smem + SM_B_LO + off) = Lo;
        }
        if (tid < H_DIM) { b1s[tid] = B1[tid]; W2s[tid] = W2[tid]; }
    }
    __syncthreads();

    // ---- GEMM1: per warp 32 edges x 64 h, K=128, 3 bf16 terms ----
    float acc[2][8][4];
    #pragma unroll
    for (int mt = 0; mt < 2; ++mt)
        #pragma unroll
        for (int nt = 0; nt < 8; ++nt)
            #pragma unroll
            for (int i = 0; i < 4; ++i) acc[mt][nt][i] = 0.0f;

    const uint32_t bRow = sbase + SM_B_HI + (L & 15) * 128;
    const uint32_t lsel = L >> 4;
    const uint32_t l7   = L & 7;

    #pragma unroll
    for (int kt = 0; kt < 8; ++kt) {
        // convert current prefetch buffer into A fragments (hi/lo)
        uint32_t ah0[4], ah1[4], al0[4], al1[4];
        {
            float2* cur = pf[kt & 1];
            // mt=0: rows g, g+8  -> cur[0..3]; mt=1: rows g+16, g+24 -> cur[4..7]
            cvt_split(cur[0], ah0[0], al0[0]);   // row g,    cols c0
            cvt_split(cur[2], ah0[1], al0[1]);   // row g+8,  cols c0
            cvt_split(cur[1], ah0[2], al0[2]);   // row g,    cols c0+8
            cvt_split(cur[3], ah0[3], al0[3]);   // row g+8,  cols c0+8
            cvt_split(cur[4], ah1[0], al1[0]);
            cvt_split(cur[6], ah1[1], al1[1]);
            cvt_split(cur[5], ah1[2], al1[2]);
            cvt_split(cur[7], ah1[3], al1[3]);
        }
        // prefetch kt+2
        if (kt < 6) {
            const float* kp = xp + (kt + 2) * 16;
            #pragma unroll
            for (int rr = 0; rr < 4; ++rr) {
                const float* rp = kp + rr * 8 * F_DIM;
                pf[kt & 1][rr * 2 + 0] = *reinterpret_cast<const float2*>(rp);
                pf[kt & 1][rr * 2 + 1] = *reinterpret_cast<const float2*>(rp + 8);
            }
        }

        const uint32_t bbase = bRow + kt * 2048;
        #pragma unroll
        for (int p = 0; p < 4; ++p) {
            // x4.trans: lanes 0-15 -> n-chunk 2p (k rows 0-7, 8-15),
            //           lanes 16-31 -> n-chunk 2p+1
            const uint32_t baddr = bbase + (((2 * p + lsel) ^ l7) << 4);
            uint32_t bh[4], bl[4];
            ldmx4t(baddr, bh);
            ldmx4t(baddr + 16384, bl);

            mma16816(acc[0][2 * p],     ah0, bh);
            mma16816(acc[1][2 * p],     ah1, bh);
            mma16816(acc[0][2 * p + 1], ah0, bh + 2);
            mma16816(acc[1][2 * p + 1], ah1, bh + 2);

            mma16816(acc[0][2 * p],     ah0, bl);
            mma16816(acc[1][2 * p],     ah1, bl);
            mma16816(acc[0][2 * p + 1], ah0, bl + 2);
            mma16816(acc[1][2 * p + 1], ah1, bl + 2);

            mma16816(acc[0][2 * p],     al0, bh);
            mma16816(acc[1][2 * p],     al1, bh);
            mma16816(acc[0][2 * p + 1], al0, bh + 2);
            mma16816(acc[1][2 * p + 1], al1, bh + 2);
        }
    }

    // ---- epilogue: bias + ssp + dot(W2); quad reduce over n ----
    {
        const float b2v = B2[0];
        #pragma unroll
        for (int mt = 0; mt < 2; ++mt) {
            #pragma unroll
            for (int half = 0; half < 2; ++half) {
                float s = 0.0f;
                #pragma unroll
                for (int nt = 0; nt < 8; ++nt) {
                    int h0 = nt * 8 + (L & 3) * 2;
                    float v0 = acc[mt][nt][half * 2 + 0];
                    float v1 = acc[mt][nt][half * 2 + 1];
                    s += ssp(v0 + b1s[h0])     * W2s[h0];
                    s += ssp(v1 + b1s[h0 + 1]) * W2s[h0 + 1];
                }
                s += __shfl_xor_sync(0xffffffffu, s, 1);
                s += __shfl_xor_sync(0xffffffffu, s, 2);
                if ((L & 3) == 0)
                    fms[m0 + mt * 16 + half * 8 + (L >> 2)] = s + b2v;
            }
        }
    }
    __syncthreads();

    // ---- per-edge force vector + 64-neighbor reduction ----
    {
        float fm = fms[tid];
        const float* up = U + ((size_t)g * TILE_E + tid) * 3;
        float v0 = fm * up[0];
        float v1 = fm * up[1];
        float v2 = fm * up[2];
        #pragma unroll
        for (int off = 16; off > 0; off >>= 1) {
            v0 += __shfl_down_sync(0xffffffffu, v0, off);
            v1 += __shfl_down_sync(0xffffffffu, v1, off);
            v2 += __shfl_down_sync(0xffffffffu, v2, off);
        }
        if (L == 0) {
            int atom = tid >> 6;
            atomicAdd(&acc6[atom * 3 + 0], v0);
            atomicAdd(&acc6[atom * 3 + 1], v1);
            atomicAdd(&acc6[atom * 3 + 2], v2);
        }
    }
    __syncthreads();

    if (tid < 6) out[(size_t)g * 6 + tid] = acc6[tid];
}

extern "C" void kernel_launch(void* const* d_in, const int* in_sizes, int n_in,
                              void* d_out, int out_size) {
    const float* X  = (const float*)d_in[0];
    const float* U  = (const float*)d_in[1];
    const float* W1 = (const float*)d_in[2];
    const float* B1 = (const float*)d_in[3];
    const float* W2 = (const float*)d_in[4];
    const float* B2 = (const float*)d_in[5];
    float* out = (float*)d_out;

    const int edges  = in_sizes[1] / 3;     // 524288
    const int blocks = edges / TILE_E;      // 4096

    cudaFuncSetAttribute(force_mapping_kernel,
                         cudaFuncAttributeMaxDynamicSharedMemorySize, SM_TOTAL);

    force_mapping_kernel<<<blocks, THREADS, SM_TOTAL>>>(X, U, W1, B1, W2, B2, out);
}